// round 1
// baseline (speedup 1.0000x reference)
#include <cuda_runtime.h>
#include <cuda_bf16.h>

// Problem constants (fixed by setup_inputs)
constexpr int B  = 8;
constexpr int N  = 16384;
constexpr int G  = 128;
constexpr int NC = 11;          // N_CLASSES
constexpr float THRESH = 0.3f;  // REG_FG_THRESH

// Output layout (concatenated, float32):
//   [0,            B*N*7)   batch_rois
//   [B*N*7,        2*B*N*7) gt_of_rois
//   [2*B*N*7,      +B*N)    gt_label_of_rois (as float)
//   [2*B*N*7+B*N,  +B*N)    reg_valid_mask

__global__ __launch_bounds__(256, 8)
void ptl_kernel(const float* __restrict__ rois,
                const float* __restrict__ gt,
                const int*   __restrict__ gt_lab,
                const float* __restrict__ assign_gt,
                const int*   __restrict__ assign_lab,
                float* __restrict__ out)
{
    // Shared GT cache for this batch
    __shared__ float4 sMin[G];     // bmin.x, bmin.y, bmin.z, vol_b
    __shared__ float4 sMax[G];     // bmax.x, bmax.y, bmax.z, (pad)
    __shared__ float  sBox[G][8];  // cx cy cz dx dy dz (-h) label_bits

    const int tid   = threadIdx.x;
    const int batch = blockIdx.x >> 6;            // 64 blocks per batch
    const int row   = ((blockIdx.x & 63) << 8) + tid;

    if (tid < G) {
        const float* gp = gt + ((size_t)batch * G + tid) * 7;
        float cx = gp[0], cy = gp[1], cz = gp[2];
        float dx = gp[3], dy = gp[4], dz = gp[5];
        float h  = gp[6];
        sMin[tid] = make_float4(cx - 0.5f * dx, cy - 0.5f * dy, cz - 0.5f * dz,
                                dx * dy * dz);
        sMax[tid] = make_float4(cx + 0.5f * dx, cy + 0.5f * dy, cz + 0.5f * dz, 0.f);
        sBox[tid][0] = cx; sBox[tid][1] = cy; sBox[tid][2] = cz;
        sBox[tid][3] = dx; sBox[tid][4] = dy; sBox[tid][5] = dz;
        sBox[tid][6] = -h;  // heading multiplied by -1 per reference
        sBox[tid][7] = __int_as_float(gt_lab[(size_t)batch * G + tid]);
    }
    __syncthreads();

    const size_t ri = (size_t)batch * N + row;
    const float* rp = rois + ri * 7;

    const float r0 = rp[0], r1 = rp[1], r2 = rp[2];
    const float r3 = rp[3], r4 = rp[4], r5 = rp[5];
    const float r6 = rp[6];

    const float aminx = r0 - 0.5f * r3, amaxx = r0 + 0.5f * r3;
    const float aminy = r1 - 0.5f * r4, amaxy = r1 + 0.5f * r4;
    const float aminz = r2 - 0.5f * r5, amaxz = r2 + 0.5f * r5;
    const float va = r3 * r4 * r5;

    // Track argmax of iou = inter/den without dividing:
    // iou_g > iou_best  <=>  inter_g * den_best > inter_best * den_g   (den > 0)
    // Strict '>' keeps the FIRST maximum -> matches jnp.argmax tie-break.
    float bi = 0.0f;   // best inter  (iou 0 baseline)
    float bd = 1.0f;   // best den
    int   bg = 0;

    #pragma unroll 8
    for (int g = 0; g < G; ++g) {
        const float4 mn = sMin[g];
        const float4 mx = sMax[g];
        float ox = fminf(amaxx, mx.x) - fmaxf(aminx, mn.x);
        float oy = fminf(amaxy, mx.y) - fmaxf(aminy, mn.y);
        float oz = fminf(amaxz, mx.z) - fmaxf(aminz, mn.z);
        ox = fmaxf(ox, 0.0f);
        oy = fmaxf(oy, 0.0f);
        oz = fmaxf(oz, 0.0f);
        const float inter = ox * oy * oz;
        const float den   = fmaxf(va + mn.w - inter, 1e-6f);
        if (inter * bd > bi * den) { bi = inter; bd = den; bg = g; }
    }

    const int  alab = assign_lab[ri];
    const bool pos1 = (alab >= 0);
    // max_ov >= THRESH  <=>  bi >= THRESH * bd
    const bool pos2 = (!pos1) && (bi >= THRESH * bd);

    float* o_rois = out;
    float* o_gt   = out + (size_t)B * N * 7;
    float* o_lab  = out + (size_t)B * N * 14;
    float* o_mask = o_lab + (size_t)B * N;

    const float* ag = assign_gt + ri * 7;

    // rois passthrough
    o_rois[ri * 7 + 0] = r0; o_rois[ri * 7 + 1] = r1; o_rois[ri * 7 + 2] = r2;
    o_rois[ri * 7 + 3] = r3; o_rois[ri * 7 + 4] = r4; o_rois[ri * 7 + 5] = r5;
    o_rois[ri * 7 + 6] = r6;

    #pragma unroll
    for (int k = 0; k < 7; ++k) {
        float gv;
        if (pos1) {
            gv = ag[k];
            if (k == 6) gv = -gv;   // assign_gt heading negated per reference
        } else if (pos2) {
            gv = sBox[bg][k];       // heading already negated at store time
        } else {
            gv = 0.0f;              // must write: d_out is poisoned
        }
        o_gt[ri * 7 + k] = gv;
    }

    int lab = pos1 ? alab : (pos2 ? __float_as_int(sBox[bg][7]) : NC);
    o_lab[ri]  = (float)lab;
    o_mask[ri] = (pos1 || pos2) ? 1.0f : 0.0f;
}

extern "C" void kernel_launch(void* const* d_in, const int* in_sizes, int n_in,
                              void* d_out, int out_size)
{
    const float* rois       = (const float*)d_in[0]; // [B,N,7]
    const float* gt         = (const float*)d_in[1]; // [B,G,7]
    const int*   gt_lab     = (const int*)  d_in[2]; // [B,G]
    const float* assign_gt  = (const float*)d_in[3]; // [B,N,7]
    const int*   assign_lab = (const int*)  d_in[4]; // [B,N]
    float*       out        = (float*)d_out;

    // B*N threads, 256 per block; 64 blocks per batch
    ptl_kernel<<<(B * N) / 256, 256>>>(rois, gt, gt_lab, assign_gt, assign_lab, out);
}

// round 2
// speedup vs baseline: 1.1936x; 1.1936x over previous
#include <cuda_runtime.h>
#include <cuda_bf16.h>

// Problem constants (fixed by setup_inputs)
constexpr int B  = 8;
constexpr int N  = 16384;
constexpr int G  = 128;
constexpr int NC = 11;          // N_CLASSES
constexpr float THRESH = 0.3f;  // REG_FG_THRESH

// Output layout (concatenated, float32):
//   [0,            B*N*7)   batch_rois
//   [B*N*7,        2*B*N*7) gt_of_rois
//   [2*B*N*7,      +B*N)    gt_label_of_rois (as float)
//   [2*B*N*7+B*N,  +B*N)    reg_valid_mask

__global__ __launch_bounds__(128)
void ptl_kernel(const float* __restrict__ rois,
                const float* __restrict__ gt,
                const int*   __restrict__ gt_lab,
                const float* __restrict__ assign_gt,
                const int*   __restrict__ assign_lab,
                float* __restrict__ out)
{
    // Shared GT cache for this batch
    __shared__ float4 sMin[G];     // bmin.x, bmin.y, bmin.z, vol_b
    __shared__ float4 sMax[G];     // bmax.x, bmax.y, bmax.z, (pad)
    __shared__ float  sBox[G][8];  // cx cy cz dx dy dz (-h) label_bits

    const int tid   = threadIdx.x;           // 0..127
    const int batch = blockIdx.x >> 7;       // 128 blocks per batch
    const int row   = ((blockIdx.x & 127) << 7) + tid;

    {
        // one GT box per thread (G == blockDim)
        const float* gp = gt + ((size_t)batch * G + tid) * 7;
        float cx = gp[0], cy = gp[1], cz = gp[2];
        float dx = gp[3], dy = gp[4], dz = gp[5];
        float h  = gp[6];
        sMin[tid] = make_float4(cx - 0.5f * dx, cy - 0.5f * dy, cz - 0.5f * dz,
                                dx * dy * dz);
        sMax[tid] = make_float4(cx + 0.5f * dx, cy + 0.5f * dy, cz + 0.5f * dz, 0.f);
        sBox[tid][0] = cx; sBox[tid][1] = cy; sBox[tid][2] = cz;
        sBox[tid][3] = dx; sBox[tid][4] = dy; sBox[tid][5] = dz;
        sBox[tid][6] = -h;  // heading multiplied by -1 per reference
        sBox[tid][7] = __int_as_float(gt_lab[(size_t)batch * G + tid]);
    }
    __syncthreads();

    const size_t ri = (size_t)batch * N + row;
    const float* rp = rois + ri * 7;

    const float r0 = rp[0], r1 = rp[1], r2 = rp[2];
    const float r3 = rp[3], r4 = rp[4], r5 = rp[5];
    const float r6 = rp[6];

    const float aminx = r0 - 0.5f * r3, amaxx = r0 + 0.5f * r3;
    const float aminy = r1 - 0.5f * r4, amaxy = r1 + 0.5f * r4;
    const float aminz = r2 - 0.5f * r5, amaxz = r2 + 0.5f * r5;
    const float va = r3 * r4 * r5;

    // iou = inter/(s - inter), s = va + vb, is strictly monotone in inter/s
    // (s - inter >= max(va,vb) >= 1, so the 1e-6 clamp never binds in-loop).
    // => argmax(iou) == argmax(inter/s); compare via inter*s_best > bi*s.
    // 4 independent trackers over blocked ranges -> 4x ILP on the carried chain.
    float bi0 = 0.f, bs0 = 1.f; int bg0 = 0;
    float bi1 = 0.f, bs1 = 1.f; int bg1 = 32;
    float bi2 = 0.f, bs2 = 1.f; int bg2 = 64;
    float bi3 = 0.f, bs3 = 1.f; int bg3 = 96;

#define IOU_STEP(BI, BS, BG, GIDX)                                          \
    {                                                                       \
        const float4 mn = sMin[(GIDX)];                                     \
        const float4 mx = sMax[(GIDX)];                                     \
        float ox = fminf(amaxx, mx.x) - fmaxf(aminx, mn.x);                 \
        float oy = fminf(amaxy, mx.y) - fmaxf(aminy, mn.y);                 \
        float oz = fminf(amaxz, mx.z) - fmaxf(aminz, mn.z);                 \
        ox = fmaxf(ox, 0.0f);                                               \
        oy = fmaxf(oy, 0.0f);                                               \
        oz = fmaxf(oz, 0.0f);                                               \
        const float inter = ox * oy * oz;                                   \
        const float s     = va + mn.w;                                      \
        if (inter * BS > BI * s) { BI = inter; BS = s; BG = (GIDX); }       \
    }

    #pragma unroll 4
    for (int j = 0; j < 32; ++j) {
        IOU_STEP(bi0, bs0, bg0, j)
        IOU_STEP(bi1, bs1, bg1, 32 + j)
        IOU_STEP(bi2, bs2, bg2, 64 + j)
        IOU_STEP(bi3, bs3, bg3, 96 + j)
    }
#undef IOU_STEP

    // Ordered merge (tracker k's indices all exceed tracker k-1's), strict '>'
    // preserves the first-max tie-break of jnp.argmax.
    if (bi1 * bs0 > bi0 * bs1) { bi0 = bi1; bs0 = bs1; bg0 = bg1; }
    if (bi2 * bs0 > bi0 * bs2) { bi0 = bi2; bs0 = bs2; bg0 = bg2; }
    if (bi3 * bs0 > bi0 * bs3) { bi0 = bi3; bs0 = bs3; bg0 = bg3; }

    const int  alab = assign_lab[ri];
    const bool pos1 = (alab >= 0);
    // max_ov >= THRESH  <=>  bi >= THRESH * clip(s - bi, 1e-6)
    const bool pos2 = (!pos1) && (bi0 >= THRESH * fmaxf(bs0 - bi0, 1e-6f));

    float* o_rois = out;
    float* o_gt   = out + (size_t)B * N * 7;
    float* o_lab  = out + (size_t)B * N * 14;
    float* o_mask = o_lab + (size_t)B * N;

    const float* ag = assign_gt + ri * 7;

    // rois passthrough
    o_rois[ri * 7 + 0] = r0; o_rois[ri * 7 + 1] = r1; o_rois[ri * 7 + 2] = r2;
    o_rois[ri * 7 + 3] = r3; o_rois[ri * 7 + 4] = r4; o_rois[ri * 7 + 5] = r5;
    o_rois[ri * 7 + 6] = r6;

    #pragma unroll
    for (int k = 0; k < 7; ++k) {
        float gv;
        if (pos1) {
            gv = ag[k];
            if (k == 6) gv = -gv;   // assign_gt heading negated per reference
        } else if (pos2) {
            gv = sBox[bg0][k];      // heading already negated at store time
        } else {
            gv = 0.0f;              // must write: d_out is poisoned
        }
        o_gt[ri * 7 + k] = gv;
    }

    int lab = pos1 ? alab : (pos2 ? __float_as_int(sBox[bg0][7]) : NC);
    o_lab[ri]  = (float)lab;
    o_mask[ri] = (pos1 || pos2) ? 1.0f : 0.0f;
}

extern "C" void kernel_launch(void* const* d_in, const int* in_sizes, int n_in,
                              void* d_out, int out_size)
{
    const float* rois       = (const float*)d_in[0]; // [B,N,7]
    const float* gt         = (const float*)d_in[1]; // [B,G,7]
    const int*   gt_lab     = (const int*)  d_in[2]; // [B,G]
    const float* assign_gt  = (const float*)d_in[3]; // [B,N,7]
    const int*   assign_lab = (const int*)  d_in[4]; // [B,N]
    float*       out        = (float*)d_out;

    // B*N threads, 128 per block; 128 blocks per batch
    ptl_kernel<<<(B * N) / 128, 128>>>(rois, gt, gt_lab, assign_gt, assign_lab, out);
}

// round 3
// speedup vs baseline: 1.1954x; 1.0015x over previous
#include <cuda_runtime.h>
#include <cuda_bf16.h>

// Problem constants (fixed by setup_inputs)
constexpr int B  = 8;
constexpr int N  = 16384;
constexpr int G  = 128;
constexpr int NC = 11;          // N_CLASSES
constexpr float THRESH = 0.3f;  // REG_FG_THRESH

constexpr int BLK = 64;                 // threads per block
constexpr int BLOCKS_PER_BATCH = N / BLK;  // 256

// Output layout (concatenated, float32):
//   [0,            B*N*7)   batch_rois
//   [B*N*7,        2*B*N*7) gt_of_rois
//   [2*B*N*7,      +B*N)    gt_label_of_rois (as float)
//   [2*B*N*7+B*N,  +B*N)    reg_valid_mask

__global__ __launch_bounds__(BLK)
void ptl_kernel(const float* __restrict__ rois,
                const float* __restrict__ gt,
                const int*   __restrict__ gt_lab,
                const float* __restrict__ assign_gt,
                const int*   __restrict__ assign_lab,
                float* __restrict__ out)
{
    // Shared GT cache for this batch
    __shared__ float4 sMin[G];     // bmin.x, bmin.y, bmin.z, vol_b
    __shared__ float4 sMax[G];     // bmax.x, bmax.y, bmax.z, (pad)
    __shared__ float  sBox[G][8];  // cx cy cz dx dy dz (-h) label_bits

    const int tid   = threadIdx.x;                    // 0..63
    const int batch = blockIdx.x / BLOCKS_PER_BATCH;
    const int row   = (blockIdx.x % BLOCKS_PER_BATCH) * BLK + tid;

    // one thread prepares 2 GT boxes (G = 2*BLK)
    #pragma unroll
    for (int r = 0; r < 2; ++r) {
        const int g = tid + r * BLK;
        const float* gp = gt + ((size_t)batch * G + g) * 7;
        float cx = gp[0], cy = gp[1], cz = gp[2];
        float dx = gp[3], dy = gp[4], dz = gp[5];
        float h  = gp[6];
        sMin[g] = make_float4(cx - 0.5f * dx, cy - 0.5f * dy, cz - 0.5f * dz,
                              dx * dy * dz);
        sMax[g] = make_float4(cx + 0.5f * dx, cy + 0.5f * dy, cz + 0.5f * dz, 0.f);
        sBox[g][0] = cx; sBox[g][1] = cy; sBox[g][2] = cz;
        sBox[g][3] = dx; sBox[g][4] = dy; sBox[g][5] = dz;
        sBox[g][6] = -h;  // heading multiplied by -1 per reference
        sBox[g][7] = __int_as_float(gt_lab[(size_t)batch * G + g]);
    }
    __syncthreads();

    const size_t ri = (size_t)batch * N + row;
    const float* rp = rois + ri * 7;

    const float r0 = rp[0], r1 = rp[1], r2 = rp[2];
    const float r3 = rp[3], r4 = rp[4], r5 = rp[5];
    const float r6 = rp[6];

    const float aminx = r0 - 0.5f * r3, amaxx = r0 + 0.5f * r3;
    const float aminy = r1 - 0.5f * r4, amaxy = r1 + 0.5f * r4;
    const float aminz = r2 - 0.5f * r5, amaxz = r2 + 0.5f * r5;
    const float va = r3 * r4 * r5;

    // iou = inter/(s - inter), s = va + vb, is strictly monotone in inter/s
    // (s - inter >= max(va,vb) >= 1, so the 1e-6 clamp never binds in-loop).
    // => argmax(iou) == argmax(inter/s); compare via inter*s_best > bi*s.
    // 4 independent trackers over blocked ranges -> 4x ILP on the carried chain.
    float bi0 = 0.f, bs0 = 1.f; int bg0 = 0;
    float bi1 = 0.f, bs1 = 1.f; int bg1 = 32;
    float bi2 = 0.f, bs2 = 1.f; int bg2 = 64;
    float bi3 = 0.f, bs3 = 1.f; int bg3 = 96;

#define IOU_STEP(BI, BS, BG, GIDX)                                          \
    {                                                                       \
        const float4 mn = sMin[(GIDX)];                                     \
        const float4 mx = sMax[(GIDX)];                                     \
        float ox = fminf(amaxx, mx.x) - fmaxf(aminx, mn.x);                 \
        float oy = fminf(amaxy, mx.y) - fmaxf(aminy, mn.y);                 \
        float oz = fminf(amaxz, mx.z) - fmaxf(aminz, mn.z);                 \
        ox = fmaxf(ox, 0.0f);                                               \
        oy = fmaxf(oy, 0.0f);                                               \
        oz = fmaxf(oz, 0.0f);                                               \
        const float inter = ox * oy * oz;                                   \
        const float s     = va + mn.w;                                      \
        if (inter * BS > BI * s) { BI = inter; BS = s; BG = (GIDX); }       \
    }

    #pragma unroll 4
    for (int j = 0; j < 32; ++j) {
        IOU_STEP(bi0, bs0, bg0, j)
        IOU_STEP(bi1, bs1, bg1, 32 + j)
        IOU_STEP(bi2, bs2, bg2, 64 + j)
        IOU_STEP(bi3, bs3, bg3, 96 + j)
    }
#undef IOU_STEP

    // Ordered merge (tracker k's indices all exceed tracker k-1's), strict '>'
    // preserves the first-max tie-break of jnp.argmax.
    if (bi1 * bs0 > bi0 * bs1) { bi0 = bi1; bs0 = bs1; bg0 = bg1; }
    if (bi2 * bs0 > bi0 * bs2) { bi0 = bi2; bs0 = bs2; bg0 = bg2; }
    if (bi3 * bs0 > bi0 * bs3) { bi0 = bi3; bs0 = bs3; bg0 = bg3; }

    const int  alab = assign_lab[ri];
    const bool pos1 = (alab >= 0);
    // max_ov >= THRESH  <=>  bi >= THRESH * clip(s - bi, 1e-6)
    const bool pos2 = (!pos1) && (bi0 >= THRESH * fmaxf(bs0 - bi0, 1e-6f));

    float* o_rois = out;
    float* o_gt   = out + (size_t)B * N * 7;
    float* o_lab  = out + (size_t)B * N * 14;
    float* o_mask = o_lab + (size_t)B * N;

    const float* ag = assign_gt + ri * 7;

    // rois passthrough
    o_rois[ri * 7 + 0] = r0; o_rois[ri * 7 + 1] = r1; o_rois[ri * 7 + 2] = r2;
    o_rois[ri * 7 + 3] = r3; o_rois[ri * 7 + 4] = r4; o_rois[ri * 7 + 5] = r5;
    o_rois[ri * 7 + 6] = r6;

    #pragma unroll
    for (int k = 0; k < 7; ++k) {
        float gv;
        if (pos1) {
            gv = ag[k];
            if (k == 6) gv = -gv;   // assign_gt heading negated per reference
        } else if (pos2) {
            gv = sBox[bg0][k];      // heading already negated at store time
        } else {
            gv = 0.0f;              // must write: d_out is poisoned
        }
        o_gt[ri * 7 + k] = gv;
    }

    int lab = pos1 ? alab : (pos2 ? __float_as_int(sBox[bg0][7]) : NC);
    o_lab[ri]  = (float)lab;
    o_mask[ri] = (pos1 || pos2) ? 1.0f : 0.0f;
}

extern "C" void kernel_launch(void* const* d_in, const int* in_sizes, int n_in,
                              void* d_out, int out_size)
{
    const float* rois       = (const float*)d_in[0]; // [B,N,7]
    const float* gt         = (const float*)d_in[1]; // [B,G,7]
    const int*   gt_lab     = (const int*)  d_in[2]; // [B,G]
    const float* assign_gt  = (const float*)d_in[3]; // [B,N,7]
    const int*   assign_lab = (const int*)  d_in[4]; // [B,N]
    float*       out        = (float*)d_out;

    // B*N threads, 64 per block; 256 blocks per batch -> 2048 blocks total
    ptl_kernel<<<(B * N) / BLK, BLK>>>(rois, gt, gt_lab, assign_gt, assign_lab, out);
}

// round 4
// speedup vs baseline: 1.6911x; 1.4147x over previous
#include <cuda_runtime.h>
#include <cuda_bf16.h>

// Problem constants (fixed by setup_inputs)
constexpr int B  = 8;
constexpr int N  = 16384;
constexpr int G  = 128;
constexpr int NC = 11;          // N_CLASSES
constexpr float THRESH = 0.3f;  // REG_FG_THRESH

// ---- packed f32x2 helpers (Blackwell sm_103a) ----
typedef unsigned long long ull;
__device__ __forceinline__ ull pk2(float lo, float hi) {
    ull r; asm("mov.b64 %0,{%1,%2};" : "=l"(r) : "f"(lo), "f"(hi)); return r;
}
__device__ __forceinline__ void upk2(ull v, float& lo, float& hi) {
    asm("mov.b64 {%0,%1},%2;" : "=f"(lo), "=f"(hi) : "l"(v));
}
__device__ __forceinline__ ull add2(ull a, ull b) {
    ull r; asm("add.rn.f32x2 %0,%1,%2;" : "=l"(r) : "l"(a), "l"(b)); return r;
}
__device__ __forceinline__ ull mul2(ull a, ull b) {
    ull r; asm("mul.rn.f32x2 %0,%1,%2;" : "=l"(r) : "l"(a), "l"(b)); return r;
}
__device__ __forceinline__ ull fma2(ull a, ull b, ull c) {
    ull r; asm("fma.rn.f32x2 %0,%1,%2,%3;" : "=l"(r) : "l"(a), "l"(b), "l"(c)); return r;
}

// Output layout (concatenated, float32):
//   [0,            B*N*7)   batch_rois
//   [B*N*7,        2*B*N*7) gt_of_rois
//   [2*B*N*7,      +B*N)    gt_label_of_rois (as float)
//   [2*B*N*7+B*N,  +B*N)    reg_valid_mask

__global__ __launch_bounds__(128)
void ptl_kernel(const float* __restrict__ rois,
                const float* __restrict__ gt,
                const int*   __restrict__ gt_lab,
                const float* __restrict__ assign_gt,
                const int*   __restrict__ assign_lab,
                float* __restrict__ out)
{
    // Shared GT cache for this batch
    // Packed filter data: pair p covers boxes e=2p, o=2p+1.
    //   sPA[p] = (-cx_e, -cx_o, -cy_e, -cy_o)
    //   sPB[p] = (-cz_e, -cz_o,  rb_e,  rb_o)   rb = half-diagonal + margin
    __shared__ float4 sPA[G / 2];
    __shared__ float4 sPB[G / 2];
    __shared__ float4 sMin[G];     // bmin.x, bmin.y, bmin.z, vol_b
    __shared__ float4 sMax[G];     // bmax.x, bmax.y, bmax.z, (pad)
    __shared__ float  sBox[G][8];  // cx cy cz dx dy dz (-h) label_bits

    const int tid   = threadIdx.x;           // 0..127
    const int batch = blockIdx.x >> 7;       // 128 blocks per batch
    const int row   = ((blockIdx.x & 127) << 7) + tid;

    {
        // one GT box per thread (G == blockDim)
        const float* gp = gt + ((size_t)batch * G + tid) * 7;
        float cx = gp[0], cy = gp[1], cz = gp[2];
        float dx = gp[3], dy = gp[4], dz = gp[5];
        float h  = gp[6];
        sMin[tid] = make_float4(cx - 0.5f * dx, cy - 0.5f * dy, cz - 0.5f * dz,
                                dx * dy * dz);
        sMax[tid] = make_float4(cx + 0.5f * dx, cy + 0.5f * dy, cz + 0.5f * dz, 0.f);
        sBox[tid][0] = cx; sBox[tid][1] = cy; sBox[tid][2] = cz;
        sBox[tid][3] = dx; sBox[tid][4] = dy; sBox[tid][5] = dz;
        sBox[tid][6] = -h;  // heading multiplied by -1 per reference
        sBox[tid][7] = __int_as_float(gt_lab[(size_t)batch * G + tid]);
        // filter radius: half-diagonal plus margin (covers all fp rounding;
        // filter must only be conservative, never rejecting inter>0 pairs)
        float rb = 0.5f * sqrtf(dx * dx + dy * dy + dz * dz) + 0.5f;
        const int p = tid >> 1, lane = tid & 1;
        float* pa = (float*)&sPA[p];
        float* pb = (float*)&sPB[p];
        pa[0 + lane] = -cx;  pa[2 + lane] = -cy;
        pb[0 + lane] = -cz;  pb[2 + lane] = rb;
    }
    __syncthreads();

    const size_t ri = (size_t)batch * N + row;
    const float* rp = rois + ri * 7;

    const float r0 = rp[0], r1 = rp[1], r2 = rp[2];
    const float r3 = rp[3], r4 = rp[4], r5 = rp[5];
    const float r6 = rp[6];

    const float aminx = r0 - 0.5f * r3, amaxx = r0 + 0.5f * r3;
    const float aminy = r1 - 0.5f * r4, amaxy = r1 + 0.5f * r4;
    const float aminz = r2 - 0.5f * r5, amaxz = r2 + 0.5f * r5;
    const float va = r3 * r4 * r5;
    const float ra = 0.5f * sqrtf(r3 * r3 + r4 * r4 + r5 * r5);

    const ull ax2 = pk2(r0, r0);
    const ull ay2 = pk2(r1, r1);
    const ull az2 = pk2(r2, r2);
    const ull ra2 = pk2(ra, ra);

    // ---- Phase 1: packed sphere-overlap filter, 2 boxes per step ----
    // Survivor mask bit g set iff dsq(g) < (ra+rb_g)^2.
    // inter>0  =>  per-axis |dc| < (da+db)/2  =>  dsq < (ra+rb)^2  (Cauchy-Schwarz),
    // so every pair with positive intersection survives; zero-inter pairs can
    // never win the strict-'>' argmax, so dropping them is exact.
    unsigned mask0, mask1, mask2, mask3;
    {
        unsigned mk[4];
        #pragma unroll
        for (int c = 0; c < 4; ++c) {
            unsigned m = 0;
            #pragma unroll
            for (int i = 0; i < 16; ++i) {
                const int p = c * 16 + i;
                const ulonglong2 qa = *(const ulonglong2*)&sPA[p];
                const ulonglong2 qb = *(const ulonglong2*)&sPB[p];
                const ull dx2 = add2(ax2, qa.x);
                const ull dy2 = add2(ay2, qa.y);
                const ull dz2 = add2(az2, qb.x);
                ull s2 = mul2(dx2, dx2);
                s2 = fma2(dy2, dy2, s2);
                s2 = fma2(dz2, dz2, s2);
                const ull rr = add2(ra2, qb.y);
                const ull rq = mul2(rr, rr);
                float s_lo, s_hi, q_lo, q_hi;
                upk2(s2, s_lo, s_hi);
                upk2(rq, q_lo, q_hi);
                if (q_lo > s_lo) m |= (1u << (2 * i));
                if (q_hi > s_hi) m |= (1u << (2 * i + 1));
            }
            mk[c] = m;
        }
        mask0 = mk[0]; mask1 = mk[1]; mask2 = mk[2]; mask3 = mk[3];
    }

    // ---- Phase 2: exact IoU-argmax over survivors (ascending g order) ----
    // iou = inter/(s - inter), s = va + vb, strictly monotone in inter/s
    // => argmax via cross-mult compare; strict '>' keeps first max (jnp.argmax).
    float bi = 0.f, bs = 1.f; int bg = 0;
    #pragma unroll
    for (int c = 0; c < 4; ++c) {
        unsigned m = (c == 0) ? mask0 : (c == 1) ? mask1 : (c == 2) ? mask2 : mask3;
        while (m) {
            const int b = __ffs(m) - 1;
            m &= m - 1;
            const int g = c * 32 + b;
            const float4 mn = sMin[g];
            const float4 mx = sMax[g];
            float ox = fminf(amaxx, mx.x) - fmaxf(aminx, mn.x);
            float oy = fminf(amaxy, mx.y) - fmaxf(aminy, mn.y);
            float oz = fminf(amaxz, mx.z) - fmaxf(aminz, mn.z);
            ox = fmaxf(ox, 0.0f);
            oy = fmaxf(oy, 0.0f);
            oz = fmaxf(oz, 0.0f);
            const float inter = ox * oy * oz;
            const float s     = va + mn.w;
            if (inter * bs > bi * s) { bi = inter; bs = s; bg = g; }
        }
    }

    const int  alab = assign_lab[ri];
    const bool pos1 = (alab >= 0);
    // max_ov >= THRESH  <=>  bi >= THRESH * clip(s - bi, 1e-6)
    const bool pos2 = (!pos1) && (bi >= THRESH * fmaxf(bs - bi, 1e-6f));

    float* o_rois = out;
    float* o_gt   = out + (size_t)B * N * 7;
    float* o_lab  = out + (size_t)B * N * 14;
    float* o_mask = o_lab + (size_t)B * N;

    const float* ag = assign_gt + ri * 7;

    // rois passthrough
    o_rois[ri * 7 + 0] = r0; o_rois[ri * 7 + 1] = r1; o_rois[ri * 7 + 2] = r2;
    o_rois[ri * 7 + 3] = r3; o_rois[ri * 7 + 4] = r4; o_rois[ri * 7 + 5] = r5;
    o_rois[ri * 7 + 6] = r6;

    #pragma unroll
    for (int k = 0; k < 7; ++k) {
        float gv;
        if (pos1) {
            gv = ag[k];
            if (k == 6) gv = -gv;   // assign_gt heading negated per reference
        } else if (pos2) {
            gv = sBox[bg][k];       // heading already negated at store time
        } else {
            gv = 0.0f;              // must write: d_out is poisoned
        }
        o_gt[ri * 7 + k] = gv;
    }

    int lab = pos1 ? alab : (pos2 ? __float_as_int(sBox[bg][7]) : NC);
    o_lab[ri]  = (float)lab;
    o_mask[ri] = (pos1 || pos2) ? 1.0f : 0.0f;
}

extern "C" void kernel_launch(void* const* d_in, const int* in_sizes, int n_in,
                              void* d_out, int out_size)
{
    const float* rois       = (const float*)d_in[0]; // [B,N,7]
    const float* gt         = (const float*)d_in[1]; // [B,G,7]
    const int*   gt_lab     = (const int*)  d_in[2]; // [B,G]
    const float* assign_gt  = (const float*)d_in[3]; // [B,N,7]
    const int*   assign_lab = (const int*)  d_in[4]; // [B,N]
    float*       out        = (float*)d_out;

    // B*N threads, 128 per block; 128 blocks per batch
    ptl_kernel<<<(B * N) / 128, 128>>>(rois, gt, gt_lab, assign_gt, assign_lab, out);
}